// round 1
// baseline (speedup 1.0000x reference)
#include <cuda_runtime.h>
#include <cstdint>

#define BB 128
#define SS 512
#define TT 256

// forward tiling: per c-chunk (64 i-rows): NREG rows in registers, RSM rows in smem
#define NREG 36
#define RSM  28
#define SMROWS (4*RSM)   // 112 rows of transitions in smem
#define FWD_SMEM (SMROWS*TT*4 + 2*TT*4)   // 114688 + 2048 = 116736 bytes

// scratch (device-global; no runtime allocation allowed)
__device__ float g_hist[BB*SS*TT];     // score vector per (b, t)  — 67 MB
__device__ float g_transT[TT*TT];      // transposed transitions for backtrack

// ---------------------------------------------------------------------------
// transpose transitions: g_transT[j][i] = trans[i][j]
// ---------------------------------------------------------------------------
__global__ void transpose_kernel(const float* __restrict__ tr) {
    int j = blockIdx.x, i = threadIdx.x;
    g_transT[j*TT + i] = tr[i*TT + j];
}

// ---------------------------------------------------------------------------
// forward: one CTA per batch. thread = (jj, c): jj = tid>>2 owns column j,
// c = tid&3 owns i-chunk [64c, 64c+64). Max-only (em hoisted, bit-exact).
// ---------------------------------------------------------------------------
__global__ void __launch_bounds__(1024, 1)
fwd_kernel(const float* __restrict__ em,
           const float* __restrict__ trans,
           const float* __restrict__ start) {
    extern __shared__ float sm[];
    float* s_tr = sm;                  // SMROWS x 256, swizzled
    float* s_sc = sm + SMROWS*TT;      // 2 x 256 double-buffered scores

    int b   = blockIdx.x;
    int tid = threadIdx.x;
    int c   = tid & 3;
    int jj  = tid >> 2;

    // stage smem transition rows (rows [64c+NREG, 64c+64) for each chunk c),
    // swizzled by 8*chunk in j so 4 chunks hit disjoint bank groups
    for (int idx = tid; idx < SMROWS*TT; idx += 1024) {
        int r = idx >> 8, j = idx & 255;
        int chunk = r / RSM;
        int k = r - chunk*RSM;
        int grow = 64*chunk + NREG + k;
        s_tr[r*TT + ((j + 8*chunk) & 255)] = trans[grow*TT + j];
    }

    // register-resident transition rows [64c, 64c+NREG), column jj
    float tr[NREG];
#pragma unroll
    for (int k = 0; k < NREG; k++)
        tr[k] = trans[(64*c + k)*TT + jj];

    const float* emb = em + (size_t)b*SS*TT;
    float*       hb  = g_hist + (size_t)b*SS*TT;

    if (c == 0) {
        float s0 = start[jj] + emb[jj];   // matches jax: start + em0
        s_sc[jj] = s0;
        hb[jj]   = s0;
    }
    __syncthreads();

    const float NEG = __int_as_float(0xff800000);   // -inf
    float e_next = emb[TT + jj];                    // prefetch em for t=1
    int cur = 0;
    int jsw = (jj + 8*c) & 255;
    const float* strc = s_tr + (c*RSM)*TT;

    for (int t = 1; t < SS; t++) {
        float ecur = e_next;
        if (t + 1 < SS) e_next = emb[(t+1)*TT + jj];

        const float* sc = s_sc + cur*TT + 64*c;
        float best = NEG;
#pragma unroll
        for (int k = 0; k < NREG; k += 4) {
            float4 s4 = *(const float4*)(sc + k);
            best = fmaxf(best, s4.x + tr[k+0]);
            best = fmaxf(best, s4.y + tr[k+1]);
            best = fmaxf(best, s4.z + tr[k+2]);
            best = fmaxf(best, s4.w + tr[k+3]);
        }
#pragma unroll
        for (int k = 0; k < RSM; k += 4) {
            float4 s4 = *(const float4*)(sc + NREG + k);
            best = fmaxf(best, s4.x + strc[(k+0)*TT + jsw]);
            best = fmaxf(best, s4.y + strc[(k+1)*TT + jsw]);
            best = fmaxf(best, s4.z + strc[(k+2)*TT + jsw]);
            best = fmaxf(best, s4.w + strc[(k+3)*TT + jsw]);
        }
        // reduce the 4 i-chunks (lanes 4q..4q+3)
        best = fmaxf(best, __shfl_xor_sync(0xffffffffu, best, 1));
        best = fmaxf(best, __shfl_xor_sync(0xffffffffu, best, 2));
        float ns = best + ecur;   // hoisted em: bit-exact (monotone rounding)
        if (c == 0) {
            s_sc[(cur^1)*TT + jj] = ns;
            hb[t*TT + jj]         = ns;
        }
        __syncthreads();
        cur ^= 1;
    }
}

// ---------------------------------------------------------------------------
// backtrack: one warp per batch. Recomputes the argmax only along the chain,
// exactly as jax: v = (score + trans) + em, first-max tie-break.
// ---------------------------------------------------------------------------
__device__ __forceinline__ unsigned ordf(float f) {
    unsigned u = __float_as_uint(f);
    return (u & 0x80000000u) ? ~u : (u | 0x80000000u);
}
__device__ __forceinline__ float ordinv(unsigned u) {
    return __uint_as_float((u & 0x80000000u) ? (u ^ 0x80000000u) : ~u);
}

__global__ void __launch_bounds__(32)
back_kernel(const float* __restrict__ em,
            const float* __restrict__ endtr,
            float* __restrict__ out) {
    __shared__ float s_em[2][TT];
    int b = blockIdx.x, L = threadIdx.x;
    const float* hb  = g_hist + (size_t)b*SS*TT;
    const float* emb = em     + (size_t)b*SS*TT;
    const float NEG = __int_as_float(0xff800000);

    // stage em row 511 into buffer (511 & 1) = 1
    {
        float4 p0 = *(const float4*)(emb + 511*TT + L*8);
        float4 p1 = *(const float4*)(emb + 511*TT + L*8 + 4);
        *(float4*)(&s_em[1][L*8])     = p0;
        *(float4*)(&s_em[1][L*8 + 4]) = p1;
    }
    __syncwarp();

    // phase A: final = hist[511] + end; max + first-argmax
    float4 h0 = *(const float4*)(hb + 511*TT + L*8);
    float4 h1 = *(const float4*)(hb + 511*TT + L*8 + 4);
    float4 e0 = *(const float4*)(endtr + L*8);
    float4 e1 = *(const float4*)(endtr + L*8 + 4);
    float bv = NEG; int bi = 0;
    {
        float v;
        v = h0.x + e0.x; if (v > bv) { bv = v; bi = L*8+0; }
        v = h0.y + e0.y; if (v > bv) { bv = v; bi = L*8+1; }
        v = h0.z + e0.z; if (v > bv) { bv = v; bi = L*8+2; }
        v = h0.w + e0.w; if (v > bv) { bv = v; bi = L*8+3; }
        v = h1.x + e1.x; if (v > bv) { bv = v; bi = L*8+4; }
        v = h1.y + e1.y; if (v > bv) { bv = v; bi = L*8+5; }
        v = h1.z + e1.z; if (v > bv) { bv = v; bi = L*8+6; }
        v = h1.w + e1.w; if (v > bv) { bv = v; bi = L*8+7; }
    }
    unsigned u  = ordf(bv);
    unsigned g  = __reduce_max_sync(0xffffffffu, u);
    unsigned mk = __ballot_sync(0xffffffffu, u == g);
    int leader  = __ffs(mk) - 1;
    int tag     = __shfl_sync(0xffffffffu, bi, leader);
    if (L == 0) {
        out[BB*SS + b]   = ordinv(g);     // best_scores[b]
        out[b*SS + 511]  = (float)tag;    // paths[b][511]
    }
    __syncwarp();

    // prefetch hist row 510
    float4 a0 = *(const float4*)(hb + 510*TT + L*8);
    float4 a1 = *(const float4*)(hb + 510*TT + L*8 + 4);

    for (int t = 511; t >= 1; t--) {
        float4 n0 = a0, n1 = a1;
        if (t > 1) {
            n0 = *(const float4*)(hb + (t-2)*TT + L*8);
            n1 = *(const float4*)(hb + (t-2)*TT + L*8 + 4);
            float4 p0 = *(const float4*)(emb + (t-1)*TT + L*8);
            float4 p1 = *(const float4*)(emb + (t-1)*TT + L*8 + 4);
            *(float4*)(&s_em[(t-1)&1][L*8])     = p0;
            *(float4*)(&s_em[(t-1)&1][L*8 + 4]) = p1;
        }
        float e = s_em[t&1][tag];
        const float* trow = g_transT + tag*TT;
        float4 t0 = *(const float4*)(trow + L*8);
        float4 t1 = *(const float4*)(trow + L*8 + 4);
        float bv2 = NEG; int bi2 = 0;
        float v;
        v = (a0.x + t0.x) + e; if (v > bv2) { bv2 = v; bi2 = L*8+0; }
        v = (a0.y + t0.y) + e; if (v > bv2) { bv2 = v; bi2 = L*8+1; }
        v = (a0.z + t0.z) + e; if (v > bv2) { bv2 = v; bi2 = L*8+2; }
        v = (a0.w + t0.w) + e; if (v > bv2) { bv2 = v; bi2 = L*8+3; }
        v = (a1.x + t1.x) + e; if (v > bv2) { bv2 = v; bi2 = L*8+4; }
        v = (a1.y + t1.y) + e; if (v > bv2) { bv2 = v; bi2 = L*8+5; }
        v = (a1.z + t1.z) + e; if (v > bv2) { bv2 = v; bi2 = L*8+6; }
        v = (a1.w + t1.w) + e; if (v > bv2) { bv2 = v; bi2 = L*8+7; }
        unsigned u2 = ordf(bv2);
        unsigned g2 = __reduce_max_sync(0xffffffffu, u2);
        unsigned m2 = __ballot_sync(0xffffffffu, u2 == g2);
        int ld2 = __ffs(m2) - 1;
        tag = __shfl_sync(0xffffffffu, bi2, ld2);
        if (L == 0) out[b*SS + (t-1)] = (float)tag;
        a0 = n0; a1 = n1;
        __syncwarp();
    }
}

// ---------------------------------------------------------------------------
// launch
// ---------------------------------------------------------------------------
extern "C" void kernel_launch(void* const* d_in, const int* in_sizes, int n_in,
                              void* d_out, int out_size) {
    const float* em    = (const float*)d_in[0];
    // d_in[1] = mask (all ones — unused)
    const float* trans = (const float*)d_in[2];
    const float* start = (const float*)d_in[3];
    const float* endt  = (const float*)d_in[4];
    float* out = (float*)d_out;

    cudaFuncSetAttribute(fwd_kernel, cudaFuncAttributeMaxDynamicSharedMemorySize, FWD_SMEM);

    transpose_kernel<<<TT, TT>>>(trans);
    fwd_kernel<<<BB, 1024, FWD_SMEM>>>(em, trans, start);
    back_kernel<<<BB, 32>>>(em, endt, out);
}

// round 2
// speedup vs baseline: 2.4049x; 2.4049x over previous
#include <cuda_runtime.h>
#include <cstdint>

#define BB 128
#define SS 512
#define TT 256

// forward: 512 threads, thread = (jj, c): c in {0,1} owns 128 i-rows.
// Per chunk: NREG rows in registers, RSM rows in swizzled smem.
#define NREG 80
#define RSM  48
#define SMROWS (2*RSM)   // 96 rows
#define FWD_SMEM ((SMROWS*TT + 2*TT)*4)   // 98304 + 2048 = 100352 bytes

// scratch (device-global; no runtime allocation allowed)
__device__ float g_hist[BB*SS*TT];     // score vector per (b, t)  — 67 MB
__device__ float g_transT[TT*TT];      // transposed transitions for backtrack

// ---------------------------------------------------------------------------
// transpose transitions: g_transT[j][i] = trans[i][j]
// ---------------------------------------------------------------------------
__global__ void transpose_kernel(const float* __restrict__ tr) {
    int j = blockIdx.x, i = threadIdx.x;
    g_transT[j*TT + i] = tr[i*TT + j];
}

// ---------------------------------------------------------------------------
// forward: one CTA per batch, 512 threads. Max-only (em hoisted, bit-exact).
// ---------------------------------------------------------------------------
__global__ void __launch_bounds__(512, 1)
fwd_kernel(const float* __restrict__ em,
           const float* __restrict__ trans,
           const float* __restrict__ start) {
    extern __shared__ float sm[];
    float* s_tr = sm;                  // SMROWS x 256, swizzled per chunk
    float* s_sc = sm + SMROWS*TT;      // 2 x 256 double-buffered scores

    int b   = blockIdx.x;
    int tid = threadIdx.x;
    int c   = tid & 1;
    int jj  = tid >> 1;

    // stage smem transition rows: chunk c keeps global rows [128c+NREG, 128c+128)
    // swizzled by 16*chunk in j so the two chunks hit disjoint bank halves
    for (int idx = tid; idx < SMROWS*TT; idx += 512) {
        int r = idx >> 8, j = idx & 255;
        int chunk = r / RSM;
        int k = r - chunk*RSM;
        int grow = 128*chunk + NREG + k;
        s_tr[r*TT + ((j + 16*chunk) & 255)] = trans[grow*TT + j];
    }

    // register-resident transition rows [128c, 128c+NREG), column jj
    float tr[NREG];
#pragma unroll
    for (int k = 0; k < NREG; k++)
        tr[k] = trans[(128*c + k)*TT + jj];

    const float* emb = em + (size_t)b*SS*TT;
    float*       hb  = g_hist + (size_t)b*SS*TT;

    if (c == 0) {
        float s0 = start[jj] + emb[jj];   // matches jax: start + em0
        s_sc[jj] = s0;
        hb[jj]   = s0;
    }
    __syncthreads();

    const float NEG = __int_as_float(0xff800000);   // -inf
    float e_next = emb[TT + jj];                    // prefetch em for t=1
    int cur = 0;
    int jsw = (jj + 16*c) & 255;
    const float* strc = s_tr + (c*RSM)*TT;

    for (int t = 1; t < SS; t++) {
        float ecur = e_next;
        if (t + 1 < SS) e_next = emb[(t+1)*TT + jj];

        const float* sc = s_sc + cur*TT + 128*c;
        float b0 = NEG, b1 = NEG, b2 = NEG, b3 = NEG;
#pragma unroll
        for (int k = 0; k < NREG; k += 4) {
            float4 s4 = *(const float4*)(sc + k);
            b0 = fmaxf(b0, s4.x + tr[k+0]);
            b1 = fmaxf(b1, s4.y + tr[k+1]);
            b2 = fmaxf(b2, s4.z + tr[k+2]);
            b3 = fmaxf(b3, s4.w + tr[k+3]);
        }
#pragma unroll
        for (int k = 0; k < RSM; k += 4) {
            float4 s4 = *(const float4*)(sc + NREG + k);
            b0 = fmaxf(b0, s4.x + strc[(k+0)*TT + jsw]);
            b1 = fmaxf(b1, s4.y + strc[(k+1)*TT + jsw]);
            b2 = fmaxf(b2, s4.z + strc[(k+2)*TT + jsw]);
            b3 = fmaxf(b3, s4.w + strc[(k+3)*TT + jsw]);
        }
        float best = fmaxf(fmaxf(b0, b1), fmaxf(b2, b3));
        // reduce the 2 i-chunks (lanes 2m / 2m+1)
        best = fmaxf(best, __shfl_xor_sync(0xffffffffu, best, 1));
        float ns = best + ecur;   // hoisted em: bit-exact (monotone rounding)
        if (c == 0) {
            s_sc[(cur^1)*TT + jj] = ns;
            hb[t*TT + jj]         = ns;
        }
        __syncthreads();
        cur ^= 1;
    }
}

// ---------------------------------------------------------------------------
// backtrack: one warp per batch. Recomputes the argmax only along the chain,
// exactly as jax: v = (score + trans) + em, first-max tie-break.
// ---------------------------------------------------------------------------
__device__ __forceinline__ unsigned ordf(float f) {
    unsigned u = __float_as_uint(f);
    return (u & 0x80000000u) ? ~u : (u | 0x80000000u);
}
__device__ __forceinline__ float ordinv(unsigned u) {
    return __uint_as_float((u & 0x80000000u) ? (u ^ 0x80000000u) : ~u);
}

__global__ void __launch_bounds__(32)
back_kernel(const float* __restrict__ em,
            const float* __restrict__ endtr,
            float* __restrict__ out) {
    __shared__ float s_em[2][TT];
    int b = blockIdx.x, L = threadIdx.x;
    const float* hb  = g_hist + (size_t)b*SS*TT;
    const float* emb = em     + (size_t)b*SS*TT;
    const float NEG = __int_as_float(0xff800000);

    // stage em row 511 into buffer (511 & 1) = 1
    {
        float4 p0 = *(const float4*)(emb + 511*TT + L*8);
        float4 p1 = *(const float4*)(emb + 511*TT + L*8 + 4);
        *(float4*)(&s_em[1][L*8])     = p0;
        *(float4*)(&s_em[1][L*8 + 4]) = p1;
    }
    __syncwarp();

    // phase A: final = hist[511] + end; max + first-argmax
    float4 h0 = *(const float4*)(hb + 511*TT + L*8);
    float4 h1 = *(const float4*)(hb + 511*TT + L*8 + 4);
    float4 e0 = *(const float4*)(endtr + L*8);
    float4 e1 = *(const float4*)(endtr + L*8 + 4);
    float bv = NEG; int bi = 0;
    {
        float v;
        v = h0.x + e0.x; if (v > bv) { bv = v; bi = L*8+0; }
        v = h0.y + e0.y; if (v > bv) { bv = v; bi = L*8+1; }
        v = h0.z + e0.z; if (v > bv) { bv = v; bi = L*8+2; }
        v = h0.w + e0.w; if (v > bv) { bv = v; bi = L*8+3; }
        v = h1.x + e1.x; if (v > bv) { bv = v; bi = L*8+4; }
        v = h1.y + e1.y; if (v > bv) { bv = v; bi = L*8+5; }
        v = h1.z + e1.z; if (v > bv) { bv = v; bi = L*8+6; }
        v = h1.w + e1.w; if (v > bv) { bv = v; bi = L*8+7; }
    }
    unsigned u  = ordf(bv);
    unsigned g  = __reduce_max_sync(0xffffffffu, u);
    unsigned mk = __ballot_sync(0xffffffffu, u == g);
    int leader  = __ffs(mk) - 1;
    int tag     = __shfl_sync(0xffffffffu, bi, leader);
    if (L == 0) {
        out[BB*SS + b]   = ordinv(g);     // best_scores[b]
        out[b*SS + 511]  = (float)tag;    // paths[b][511]
    }
    __syncwarp();

    // prefetch hist row 510
    float4 a0 = *(const float4*)(hb + 510*TT + L*8);
    float4 a1 = *(const float4*)(hb + 510*TT + L*8 + 4);

    for (int t = 511; t >= 1; t--) {
        float4 n0 = a0, n1 = a1;
        if (t > 1) {
            n0 = *(const float4*)(hb + (t-2)*TT + L*8);
            n1 = *(const float4*)(hb + (t-2)*TT + L*8 + 4);
            float4 p0 = *(const float4*)(emb + (t-1)*TT + L*8);
            float4 p1 = *(const float4*)(emb + (t-1)*TT + L*8 + 4);
            *(float4*)(&s_em[(t-1)&1][L*8])     = p0;
            *(float4*)(&s_em[(t-1)&1][L*8 + 4]) = p1;
        }
        float e = s_em[t&1][tag];
        const float* trow = g_transT + tag*TT;
        float4 t0 = *(const float4*)(trow + L*8);
        float4 t1 = *(const float4*)(trow + L*8 + 4);
        float bv2 = NEG; int bi2 = 0;
        float v;
        v = (a0.x + t0.x) + e; if (v > bv2) { bv2 = v; bi2 = L*8+0; }
        v = (a0.y + t0.y) + e; if (v > bv2) { bv2 = v; bi2 = L*8+1; }
        v = (a0.z + t0.z) + e; if (v > bv2) { bv2 = v; bi2 = L*8+2; }
        v = (a0.w + t0.w) + e; if (v > bv2) { bv2 = v; bi2 = L*8+3; }
        v = (a1.x + t1.x) + e; if (v > bv2) { bv2 = v; bi2 = L*8+4; }
        v = (a1.y + t1.y) + e; if (v > bv2) { bv2 = v; bi2 = L*8+5; }
        v = (a1.z + t1.z) + e; if (v > bv2) { bv2 = v; bi2 = L*8+6; }
        v = (a1.w + t1.w) + e; if (v > bv2) { bv2 = v; bi2 = L*8+7; }
        unsigned u2 = ordf(bv2);
        unsigned g2 = __reduce_max_sync(0xffffffffu, u2);
        unsigned m2 = __ballot_sync(0xffffffffu, u2 == g2);
        int ld2 = __ffs(m2) - 1;
        tag = __shfl_sync(0xffffffffu, bi2, ld2);
        if (L == 0) out[b*SS + (t-1)] = (float)tag;
        a0 = n0; a1 = n1;
        __syncwarp();
    }
}

// ---------------------------------------------------------------------------
// launch
// ---------------------------------------------------------------------------
extern "C" void kernel_launch(void* const* d_in, const int* in_sizes, int n_in,
                              void* d_out, int out_size) {
    const float* em    = (const float*)d_in[0];
    // d_in[1] = mask (all ones — unused)
    const float* trans = (const float*)d_in[2];
    const float* start = (const float*)d_in[3];
    const float* endt  = (const float*)d_in[4];
    float* out = (float*)d_out;

    cudaFuncSetAttribute(fwd_kernel, cudaFuncAttributeMaxDynamicSharedMemorySize, FWD_SMEM);

    transpose_kernel<<<TT, TT>>>(trans);
    fwd_kernel<<<BB, 512, FWD_SMEM>>>(em, trans, start);
    back_kernel<<<BB, 32>>>(em, endt, out);
}